// round 1
// baseline (speedup 1.0000x reference)
#include <cuda_runtime.h>
#include <math.h>

#define TDIM 8192
#define NFEAT 32
#define NT 512
#define CHUNK (TDIM / NT)   // 16 elements per thread
#define MS 16
#define NEAR_END 6553       // int(8192*0.8); mask is P > NEAR_END

__global__ __launch_bounds__(NT, 1)
void bcpd_kernel(const float* __restrict__ x,
                 const float* __restrict__ prior_mean,
                 const float* __restrict__ prior_var,
                 const float* __restrict__ noise_var,
                 float* __restrict__ out)
{
    __shared__ float m_sh[TDIM];      // 32 KB: per-t means (never re-read after caching to regs)
    __shared__ float ws1[16], ws2[16];
    __shared__ float red[NT];
    __shared__ float tot_sh[2];

    const int b    = blockIdx.x;
    const int tid  = threadIdx.x;
    const int lane = tid & 31;
    const int warp = tid >> 5;

    const float4* xb = reinterpret_cast<const float4*>(x + (size_t)b * TDIM * NFEAT);

    // ---------------- Phase 1: feature means (coalesced float4 streaming) -------
    // Each warp iter: 32 lanes x float4 = 128 floats = 4 timesteps.
    // lanes [8k, 8k+7] cover timestep t4*4+k; 3-step xor reduce within 8-lane group.
    #pragma unroll 4
    for (int t4 = warp; t4 < TDIM / 4; t4 += 16) {
        float4 v = xb[t4 * 32 + lane];
        float s = (v.x + v.y) + (v.z + v.w);
        s += __shfl_xor_sync(0xffffffffu, s, 1);
        s += __shfl_xor_sync(0xffffffffu, s, 2);
        s += __shfl_xor_sync(0xffffffffu, s, 4);
        if ((lane & 7) == 0) m_sh[t4 * 4 + (lane >> 3)] = s * (1.0f / NFEAT);
    }
    __syncthreads();

    // ---------------- Phase 2: block prefix scan of (m, m^2) --------------------
    float loc[CHUNK];
    float c1 = 0.f, c2 = 0.f;
    const int base = tid * CHUNK;
    #pragma unroll
    for (int j = 0; j < CHUNK; ++j) {
        float mv = m_sh[base + j];
        loc[j] = mv;
        c1 += mv;
        c2 += mv * mv;
    }
    // warp-level inclusive scan of chunk sums
    float i1 = c1, i2 = c2;
    #pragma unroll
    for (int d = 1; d < 32; d <<= 1) {
        float a = __shfl_up_sync(0xffffffffu, i1, d);
        float bb = __shfl_up_sync(0xffffffffu, i2, d);
        if (lane >= d) { i1 += a; i2 += bb; }
    }
    if (lane == 31) { ws1[warp] = i1; ws2[warp] = i2; }
    __syncthreads();
    if (warp == 0) {
        float a1 = (lane < 16) ? ws1[lane] : 0.f;
        float a2 = (lane < 16) ? ws2[lane] : 0.f;
        #pragma unroll
        for (int d = 1; d < 16; d <<= 1) {
            float u = __shfl_up_sync(0xffffffffu, a1, d);
            float v = __shfl_up_sync(0xffffffffu, a2, d);
            if (lane >= d) { a1 += u; a2 += v; }
        }
        if (lane < 16) { ws1[lane] = a1; ws2[lane] = a2; }
    }
    __syncthreads();
    const float off1 = (warp > 0) ? ws1[warp - 1] : 0.f;
    const float off2 = (warp > 0) ? ws2[warp - 1] : 0.f;
    // exclusive prefix at start of this thread's chunk
    float cs1 = off1 + (i1 - c1);
    float cs2 = off2 + (i2 - c2);
    const float totS = ws1[15];
    const float totQ = ws2[15];

    // ---------------- Phase 3: scalars + per-P Bayes factor ---------------------
    const float pm = prior_mean[0];
    const float pv = log1pf(expf(prior_var[0]));   // softplus
    const float nv = log1pf(expf(noise_var[0]));
    const float inv_pv = 1.0f / pv;
    const float inv_nv = 1.0f / nv;
    const float l2pnv  = logf(2.0f * 3.14159265358979323846f * nv);
    const float pm2pv  = pm * pm * inv_pv;

    // log marginal likelihood
    auto log_ml = [&](float n, float mean, float var) -> float {
        float post_var  = 1.0f / (inv_pv + n * inv_nv);
        float post_mean = post_var * (pm * inv_pv + n * mean * inv_nv);
        return -0.5f * n * l2pnv + 0.5f * logf(post_var * inv_pv)
               - 0.5f * (n * var * inv_nv + mean * mean * n * inv_nv
                         - post_mean * post_mean / post_var + pm2pv);
    };

    // whole-window log-ml (same for all P in this row)
    const float nW = (float)TDIM;
    const float meanW = totS / nW;
    const float varW  = fmaxf((totQ - totS * totS / nW) / (nW - 1.0f), 1e-8f);
    const float lmlW  = log_ml(nW, meanW, varW);

    #pragma unroll
    for (int j = 0; j < CHUNK; ++j) {
        const int P = base + j;
        const float mv = loc[j];
        float bf;
        if (P >= MS && P < TDIM - MS) {
            const float nL = (float)P;
            const float nR = (float)(TDIM - P);
            const float sumL = cs1, sqL = cs2;
            const float sumR = totS - cs1, sqR = totQ - cs2;
            const float meanL = sumL / nL;
            const float varL  = fmaxf((sqL - sumL * sumL / nL) / (nL - 1.0f), 1e-8f);
            const float meanR = sumR / nR;
            const float varR  = fmaxf((sqR - sumR * sumR / nR) / (nR - 1.0f), 1e-8f);
            bf = log_ml(nL, meanL, varL) + log_ml(nR, meanR, varR) - lmlW;
        } else {
            bf = -INFINITY;
        }
        loc[j] = bf;            // bf now lives in registers
        cs1 += mv;
        cs2 += mv * mv;
    }

    // ---------------- Phase 4: softmax-style reductions -------------------------
    // 4a: block max
    float vmax = -INFINITY;
    #pragma unroll
    for (int j = 0; j < CHUNK; ++j) vmax = fmaxf(vmax, loc[j]);
    red[tid] = vmax;
    __syncthreads();
    for (int s = NT / 2; s > 0; s >>= 1) {
        if (tid < s) red[tid] = fmaxf(red[tid], red[tid + s]);
        __syncthreads();
    }
    const float bfmax = red[0];
    __syncthreads();

    // 4b: total exp sum
    float s_all = 0.f, s_msk = 0.f;
    #pragma unroll
    for (int j = 0; j < CHUNK; ++j) {
        const int P = base + j;
        const float e = expf(loc[j] - bfmax);   // exp(-inf)=0 handles invalid P
        s_all += e;
        if (P > NEAR_END) s_msk += e;
    }
    red[tid] = s_all;
    __syncthreads();
    for (int s = NT / 2; s > 0; s >>= 1) {
        if (tid < s) red[tid] += red[tid + s];
        __syncthreads();
    }
    if (tid == 0) tot_sh[0] = red[0];
    __syncthreads();
    red[tid] = s_msk;
    __syncthreads();
    for (int s = NT / 2; s > 0; s >>= 1) {
        if (tid < s) red[tid] += red[tid + s];
        __syncthreads();
    }
    if (tid == 0) {
        const float denom = tot_sh[0];
        const float weight = red[0] / denom;
        const float conf = 1.0f / (1.0f + expf(-bfmax));
        out[b] = conf * weight;
    }
}

extern "C" void kernel_launch(void* const* d_in, const int* in_sizes, int n_in,
                              void* d_out, int out_size)
{
    const float* x  = (const float*)d_in[0];
    const float* pm = (const float*)d_in[1];
    const float* pv = (const float*)d_in[2];
    const float* nv = (const float*)d_in[3];
    float* out = (float*)d_out;
    bcpd_kernel<<<out_size, NT>>>(x, pm, pv, nv, out);
}

// round 3
// speedup vs baseline: 1.4031x; 1.4031x over previous
#include <cuda_runtime.h>
#include <math.h>

#define B_DIM 128
#define TDIM 8192
#define NFEAT 32
#define MS 16
#define NEAR_END 6553       // int(8192*0.8); mask is P > NEAR_END

// ---- scratch for per-timestep means (4 MB) --------------------------------
__device__ float g_mean[B_DIM * TDIM];

// ============================================================================
// Kernel A: feature-mean streaming reduction.
// x viewed as [B*T, 32] floats = [B*T/4 * 32] float4 rows of 8 float4 each...
// Unit of work: t4 = 4 consecutive timesteps = 32 float4 (512 B), one warp-load.
// lanes [8k..8k+7] cover timestep t4*4+k; 3-step xor reduce in 8-lane groups.
// 2048 blocks x 256 threads = 16384 warps; TOTAL_T4 = 262144 = 16384*16,
// processed as 4 outer iters x 4-way unrolled strided loads (exact, no bounds).
// ============================================================================
#define MEAN_GRID 2048
#define MEAN_NT   256
#define TOTAL_T4  (B_DIM * TDIM / 4)        // 262144
#define NWARPS    (MEAN_GRID * MEAN_NT / 32) // 16384

__global__ __launch_bounds__(MEAN_NT)
void mean_kernel(const float4* __restrict__ x4)
{
    const int lane = threadIdx.x & 31;
    const int wg   = (blockIdx.x * MEAN_NT + threadIdx.x) >> 5;

    #pragma unroll
    for (int it = 0; it < TOTAL_T4 / (4 * NWARPS); ++it) {
        const int t4_0 = wg + it * 4 * NWARPS;
        // 4 independent 512B loads in flight
        float4 v0 = x4[(size_t)(t4_0 + 0 * NWARPS) * 32 + lane];
        float4 v1 = x4[(size_t)(t4_0 + 1 * NWARPS) * 32 + lane];
        float4 v2 = x4[(size_t)(t4_0 + 2 * NWARPS) * 32 + lane];
        float4 v3 = x4[(size_t)(t4_0 + 3 * NWARPS) * 32 + lane];

        float s0 = (v0.x + v0.y) + (v0.z + v0.w);
        float s1 = (v1.x + v1.y) + (v1.z + v1.w);
        float s2 = (v2.x + v2.y) + (v2.z + v2.w);
        float s3 = (v3.x + v3.y) + (v3.z + v3.w);
        #pragma unroll
        for (int d = 1; d < 8; d <<= 1) {
            s0 += __shfl_xor_sync(0xffffffffu, s0, d);
            s1 += __shfl_xor_sync(0xffffffffu, s1, d);
            s2 += __shfl_xor_sync(0xffffffffu, s2, d);
            s3 += __shfl_xor_sync(0xffffffffu, s3, d);
        }
        if ((lane & 7) == 0) {
            const int r = lane >> 3;
            g_mean[(t4_0 + 0 * NWARPS) * 4 + r] = s0 * (1.0f / NFEAT);
            g_mean[(t4_0 + 1 * NWARPS) * 4 + r] = s1 * (1.0f / NFEAT);
            g_mean[(t4_0 + 2 * NWARPS) * 4 + r] = s2 * (1.0f / NFEAT);
            g_mean[(t4_0 + 3 * NWARPS) * 4 + r] = s3 * (1.0f / NFEAT);
        }
    }
}

// ============================================================================
// Kernel B: per-row prefix scan + Bayes factor + softmax reductions.
// One CTA (512 threads) per batch row; means read from g_mean.
// ============================================================================
#define NT 512
#define CHUNK (TDIM / NT)   // 16

__global__ __launch_bounds__(NT, 1)
void score_kernel(const float* __restrict__ prior_mean,
                  const float* __restrict__ prior_var,
                  const float* __restrict__ noise_var,
                  float* __restrict__ out)
{
    __shared__ float ws1[16], ws2[16];
    __shared__ float red[NT];
    __shared__ float tot_sh[1];

    const int b    = blockIdx.x;
    const int tid  = threadIdx.x;
    const int lane = tid & 31;
    const int warp = tid >> 5;
    const int base = tid * CHUNK;

    // ---- load this thread's 16 means (4x float4) + chunk sums -----------------
    float loc[CHUNK];
    const float4* mrow = reinterpret_cast<const float4*>(g_mean + (size_t)b * TDIM);
    float c1 = 0.f, c2 = 0.f;
    #pragma unroll
    for (int q = 0; q < CHUNK / 4; ++q) {
        float4 v = mrow[tid * (CHUNK / 4) + q];
        loc[q * 4 + 0] = v.x; loc[q * 4 + 1] = v.y;
        loc[q * 4 + 2] = v.z; loc[q * 4 + 3] = v.w;
        c1 += (v.x + v.y) + (v.z + v.w);
        c2 += (v.x * v.x + v.y * v.y) + (v.z * v.z + v.w * v.w);
    }

    // ---- block prefix scan of chunk sums (m, m^2) -----------------------------
    float i1 = c1, i2 = c2;
    #pragma unroll
    for (int d = 1; d < 32; d <<= 1) {
        float a = __shfl_up_sync(0xffffffffu, i1, d);
        float bb = __shfl_up_sync(0xffffffffu, i2, d);
        if (lane >= d) { i1 += a; i2 += bb; }
    }
    if (lane == 31) { ws1[warp] = i1; ws2[warp] = i2; }
    __syncthreads();
    if (warp == 0) {
        float a1 = (lane < 16) ? ws1[lane] : 0.f;
        float a2 = (lane < 16) ? ws2[lane] : 0.f;
        #pragma unroll
        for (int d = 1; d < 16; d <<= 1) {
            float u = __shfl_up_sync(0xffffffffu, a1, d);
            float v = __shfl_up_sync(0xffffffffu, a2, d);
            if (lane >= d) { a1 += u; a2 += v; }
        }
        if (lane < 16) { ws1[lane] = a1; ws2[lane] = a2; }
    }
    __syncthreads();
    const float off1 = (warp > 0) ? ws1[warp - 1] : 0.f;
    const float off2 = (warp > 0) ? ws2[warp - 1] : 0.f;
    float cs1 = off1 + (i1 - c1);   // exclusive prefix at chunk start
    float cs2 = off2 + (i2 - c2);
    const float totS = ws1[15];
    const float totQ = ws2[15];

    // ---- scalars --------------------------------------------------------------
    const float pm = prior_mean[0];
    const float pv = log1pf(expf(prior_var[0]));   // softplus
    const float nv = log1pf(expf(noise_var[0]));
    const float inv_pv = 1.0f / pv;
    const float inv_nv = 1.0f / nv;
    const float l2pnv  = logf(2.0f * 3.14159265358979323846f * nv);
    const float pm2pv  = pm * pm * inv_pv;

    auto log_ml = [&](float n, float mean, float var) -> float {
        float post_var  = 1.0f / (inv_pv + n * inv_nv);
        float post_mean = post_var * (pm * inv_pv + n * mean * inv_nv);
        return -0.5f * n * l2pnv + 0.5f * logf(post_var * inv_pv)
               - 0.5f * (n * var * inv_nv + mean * mean * n * inv_nv
                         - post_mean * post_mean / post_var + pm2pv);
    };

    const float nW = (float)TDIM;
    const float meanW = totS / nW;
    const float varW  = fmaxf((totQ - totS * totS / nW) / (nW - 1.0f), 1e-8f);
    const float lmlW  = log_ml(nW, meanW, varW);

    // ---- per-P Bayes factor ---------------------------------------------------
    #pragma unroll
    for (int j = 0; j < CHUNK; ++j) {
        const int P = base + j;
        const float mv = loc[j];
        float bf;
        if (P >= MS && P < TDIM - MS) {
            const float nL = (float)P;
            const float nR = (float)(TDIM - P);
            const float sumR = totS - cs1, sqR = totQ - cs2;
            const float meanL = cs1 / nL;
            const float varL  = fmaxf((cs2 - cs1 * cs1 / nL) / (nL - 1.0f), 1e-8f);
            const float meanR = sumR / nR;
            const float varR  = fmaxf((sqR - sumR * sumR / nR) / (nR - 1.0f), 1e-8f);
            bf = log_ml(nL, meanL, varL) + log_ml(nR, meanR, varR) - lmlW;
        } else {
            bf = -INFINITY;
        }
        loc[j] = bf;
        cs1 += mv;
        cs2 += mv * mv;
    }

    // ---- softmax-style reductions --------------------------------------------
    float vmax = -INFINITY;
    #pragma unroll
    for (int j = 0; j < CHUNK; ++j) vmax = fmaxf(vmax, loc[j]);
    red[tid] = vmax;
    __syncthreads();
    for (int s = NT / 2; s > 0; s >>= 1) {
        if (tid < s) red[tid] = fmaxf(red[tid], red[tid + s]);
        __syncthreads();
    }
    const float bfmax = red[0];
    __syncthreads();

    float s_all = 0.f, s_msk = 0.f;
    #pragma unroll
    for (int j = 0; j < CHUNK; ++j) {
        const int P = base + j;
        const float e = expf(loc[j] - bfmax);
        s_all += e;
        if (P > NEAR_END) s_msk += e;
    }
    red[tid] = s_all;
    __syncthreads();
    for (int s = NT / 2; s > 0; s >>= 1) {
        if (tid < s) red[tid] += red[tid + s];
        __syncthreads();
    }
    if (tid == 0) tot_sh[0] = red[0];
    __syncthreads();
    red[tid] = s_msk;
    __syncthreads();
    for (int s = NT / 2; s > 0; s >>= 1) {
        if (tid < s) red[tid] += red[tid + s];
        __syncthreads();
    }
    if (tid == 0) {
        const float weight = red[0] / tot_sh[0];
        const float conf = 1.0f / (1.0f + expf(-bfmax));
        out[b] = conf * weight;
    }
}

extern "C" void kernel_launch(void* const* d_in, const int* in_sizes, int n_in,
                              void* d_out, int out_size)
{
    const float4* x4 = (const float4*)d_in[0];
    const float* pm = (const float*)d_in[1];
    const float* pv = (const float*)d_in[2];
    const float* nv = (const float*)d_in[3];
    float* out = (float*)d_out;
    mean_kernel<<<MEAN_GRID, MEAN_NT>>>(x4);
    score_kernel<<<out_size, NT>>>(pm, pv, nv, out);
}

// round 4
// speedup vs baseline: 1.7522x; 1.2488x over previous
#include <cuda_runtime.h>
#include <math.h>

#define B_DIM 128
#define TDIM 8192
#define NFEAT 32
#define MS 16
#define NEAR_END 6553       // int(8192*0.8); mask is P > NEAR_END

// ---- scratch for per-timestep means (4 MB) --------------------------------
__device__ float g_mean[B_DIM * TDIM];

// ============================================================================
// Kernel A: feature-mean streaming reduction (unchanged layout, + __ldcs).
// ============================================================================
#define MEAN_GRID 2048
#define MEAN_NT   256
#define TOTAL_T4  (B_DIM * TDIM / 4)         // 262144
#define NWARPS    (MEAN_GRID * MEAN_NT / 32) // 16384

__global__ __launch_bounds__(MEAN_NT)
void mean_kernel(const float4* __restrict__ x4)
{
    const int lane = threadIdx.x & 31;
    const int wg   = (blockIdx.x * MEAN_NT + threadIdx.x) >> 5;

    #pragma unroll
    for (int it = 0; it < TOTAL_T4 / (4 * NWARPS); ++it) {
        const int t4_0 = wg + it * 4 * NWARPS;
        float4 v0 = __ldcs(&x4[(size_t)(t4_0 + 0 * NWARPS) * 32 + lane]);
        float4 v1 = __ldcs(&x4[(size_t)(t4_0 + 1 * NWARPS) * 32 + lane]);
        float4 v2 = __ldcs(&x4[(size_t)(t4_0 + 2 * NWARPS) * 32 + lane]);
        float4 v3 = __ldcs(&x4[(size_t)(t4_0 + 3 * NWARPS) * 32 + lane]);

        float s0 = (v0.x + v0.y) + (v0.z + v0.w);
        float s1 = (v1.x + v1.y) + (v1.z + v1.w);
        float s2 = (v2.x + v2.y) + (v2.z + v2.w);
        float s3 = (v3.x + v3.y) + (v3.z + v3.w);
        #pragma unroll
        for (int d = 1; d < 8; d <<= 1) {
            s0 += __shfl_xor_sync(0xffffffffu, s0, d);
            s1 += __shfl_xor_sync(0xffffffffu, s1, d);
            s2 += __shfl_xor_sync(0xffffffffu, s2, d);
            s3 += __shfl_xor_sync(0xffffffffu, s3, d);
        }
        if ((lane & 7) == 0) {
            const int r = lane >> 3;
            g_mean[(t4_0 + 0 * NWARPS) * 4 + r] = s0 * (1.0f / NFEAT);
            g_mean[(t4_0 + 1 * NWARPS) * 4 + r] = s1 * (1.0f / NFEAT);
            g_mean[(t4_0 + 2 * NWARPS) * 4 + r] = s2 * (1.0f / NFEAT);
            g_mean[(t4_0 + 3 * NWARPS) * 4 + r] = s3 * (1.0f / NFEAT);
        }
    }
}

// ============================================================================
// Kernel B: per-row prefix scan + simplified Bayes factor + softmax.
// 1024 threads/CTA (32 warps), CHUNK=8, warp-shuffle reductions.
//
// Simplification of bf = lmlL + lmlR - lmlW:
//   * -n/2*log(2*pi*nv) terms cancel exactly (nL+nR=nW) -> dropped.
//   * logs fuse: -0.5*log(pv*aL*aR/aW),  a(n) = 1/pv + n/nv
//   * all whole-window terms -> constant K.
// bf = -0.5*__logf(cpv*aL*aR)
//      -0.5*inv_nv*(nL*vL + sL^2/nL + nR*vR + sR^2/nR)
//      +0.5*(btL^2/aL + btR^2/aR) + K,     bt(s) = pm/pv + s/nv
// ============================================================================
#define NT 1024
#define CHUNK (TDIM / NT)   // 8

__global__ __launch_bounds__(NT, 1)
void score_kernel(const float* __restrict__ prior_mean,
                  const float* __restrict__ prior_var,
                  const float* __restrict__ noise_var,
                  float* __restrict__ out)
{
    __shared__ float ws1[32], ws2[32];
    __shared__ float rwarp[32], rwarp2[32];
    __shared__ float bcast[2];

    const int b    = blockIdx.x;
    const int tid  = threadIdx.x;
    const int lane = tid & 31;
    const int warp = tid >> 5;
    const int base = tid * CHUNK;

    // ---- load this thread's 8 means (2x float4) + chunk sums -----------------
    float loc[CHUNK];
    const float4* mrow = reinterpret_cast<const float4*>(g_mean + (size_t)b * TDIM);
    float c1 = 0.f, c2 = 0.f;
    #pragma unroll
    for (int q = 0; q < CHUNK / 4; ++q) {
        float4 v = mrow[tid * (CHUNK / 4) + q];
        loc[q * 4 + 0] = v.x; loc[q * 4 + 1] = v.y;
        loc[q * 4 + 2] = v.z; loc[q * 4 + 3] = v.w;
        c1 += (v.x + v.y) + (v.z + v.w);
        c2 += (v.x * v.x + v.y * v.y) + (v.z * v.z + v.w * v.w);
    }

    // ---- block prefix scan of chunk sums (m, m^2) -----------------------------
    float i1 = c1, i2 = c2;
    #pragma unroll
    for (int d = 1; d < 32; d <<= 1) {
        float a = __shfl_up_sync(0xffffffffu, i1, d);
        float bb = __shfl_up_sync(0xffffffffu, i2, d);
        if (lane >= d) { i1 += a; i2 += bb; }
    }
    if (lane == 31) { ws1[warp] = i1; ws2[warp] = i2; }
    __syncthreads();
    if (warp == 0) {
        float a1 = ws1[lane];
        float a2 = ws2[lane];
        #pragma unroll
        for (int d = 1; d < 32; d <<= 1) {
            float u = __shfl_up_sync(0xffffffffu, a1, d);
            float v = __shfl_up_sync(0xffffffffu, a2, d);
            if (lane >= d) { a1 += u; a2 += v; }
        }
        ws1[lane] = a1; ws2[lane] = a2;
    }
    __syncthreads();
    const float off1 = (warp > 0) ? ws1[warp - 1] : 0.f;
    const float off2 = (warp > 0) ? ws2[warp - 1] : 0.f;
    float cs1 = off1 + (i1 - c1);   // exclusive prefix at chunk start
    float cs2 = off2 + (i2 - c2);
    const float totS = ws1[31];
    const float totQ = ws2[31];

    // ---- scalar constants -----------------------------------------------------
    const float pm = prior_mean[0];
    const float pv = log1pf(expf(prior_var[0]));   // softplus (full precision, once)
    const float nv = log1pf(expf(noise_var[0]));
    const float inv_pv = 1.0f / pv;
    const float inv_nv = 1.0f / nv;
    const float pmipv  = pm * inv_pv;
    const float pm2pv  = pm * pm * inv_pv;

    // whole-window constants
    const float nW = (float)TDIM;
    const float aW = inv_pv + nW * inv_nv;
    const float rcp_aW = 1.0f / aW;
    const float btW = pmipv + totS * inv_nv;
    const float s2nW = totS * totS / nW;
    const float vW = fmaxf((totQ - s2nW) / (nW - 1.0f), 1e-8f);
    const float K = 0.5f * ((nW * vW + s2nW) * inv_nv - btW * btW * rcp_aW - pm2pv);
    const float cpv = pv * rcp_aW;   // log arg scale: cpv*aL*aR = pv*aL*aR/aW

    // ---- per-P Bayes factor ---------------------------------------------------
    #pragma unroll
    for (int j = 0; j < CHUNK; ++j) {
        const int P = base + j;
        const float mv = loc[j];
        float bf;
        if (P >= MS && P < TDIM - MS) {
            const float fL = (float)P;
            const float fR = (float)(TDIM - P);
            const float sL = cs1, qL = cs2;
            const float sR = totS - cs1, qR = totQ - cs2;

            const float rL   = __fdividef(1.0f, fL);
            const float rLm1 = __fdividef(1.0f, fL - 1.0f);
            const float rR   = __fdividef(1.0f, fR);
            const float rRm1 = __fdividef(1.0f, fR - 1.0f);

            const float s2nL = sL * sL * rL;
            const float vL   = fmaxf((qL - s2nL) * rLm1, 1e-8f);
            const float s2nR = sR * sR * rR;
            const float vR   = fmaxf((qR - s2nR) * rRm1, 1e-8f);

            const float aL = inv_pv + fL * inv_nv;
            const float aR = inv_pv + fR * inv_nv;
            const float btL = pmipv + sL * inv_nv;
            const float btR = pmipv + sR * inv_nv;
            const float quad = btL * btL * __fdividef(1.0f, aL)
                             + btR * btR * __fdividef(1.0f, aR);

            bf = -0.5f * __logf(cpv * aL * aR)
                 - 0.5f * ((fL * vL + s2nL + fR * vR + s2nR) * inv_nv)
                 + 0.5f * quad + K;
        } else {
            bf = -INFINITY;
        }
        loc[j] = bf;
        cs1 += mv;
        cs2 += mv * mv;
    }

    // ---- reductions: max, then (sum, masked sum) ------------------------------
    float vmax = -INFINITY;
    #pragma unroll
    for (int j = 0; j < CHUNK; ++j) vmax = fmaxf(vmax, loc[j]);
    #pragma unroll
    for (int d = 16; d > 0; d >>= 1)
        vmax = fmaxf(vmax, __shfl_xor_sync(0xffffffffu, vmax, d));
    if (lane == 0) rwarp[warp] = vmax;
    __syncthreads();
    if (warp == 0) {
        float m = rwarp[lane];
        #pragma unroll
        for (int d = 16; d > 0; d >>= 1)
            m = fmaxf(m, __shfl_xor_sync(0xffffffffu, m, d));
        if (lane == 0) bcast[0] = m;
    }
    __syncthreads();
    const float bfmax = bcast[0];

    float s_all = 0.f, s_msk = 0.f;
    #pragma unroll
    for (int j = 0; j < CHUNK; ++j) {
        const int P = base + j;
        const float e = __expf(loc[j] - bfmax);   // exp(-inf)=0 for invalid P
        s_all += e;
        if (P > NEAR_END) s_msk += e;
    }
    #pragma unroll
    for (int d = 16; d > 0; d >>= 1) {
        s_all += __shfl_xor_sync(0xffffffffu, s_all, d);
        s_msk += __shfl_xor_sync(0xffffffffu, s_msk, d);
    }
    if (lane == 0) { rwarp[warp] = s_all; rwarp2[warp] = s_msk; }
    __syncthreads();
    if (warp == 0) {
        float a = rwarp[lane];
        float m = rwarp2[lane];
        #pragma unroll
        for (int d = 16; d > 0; d >>= 1) {
            a += __shfl_xor_sync(0xffffffffu, a, d);
            m += __shfl_xor_sync(0xffffffffu, m, d);
        }
        if (lane == 0) {
            const float weight = m / a;
            const float conf = 1.0f / (1.0f + __expf(-bfmax));
            out[b] = conf * weight;
        }
    }
}

extern "C" void kernel_launch(void* const* d_in, const int* in_sizes, int n_in,
                              void* d_out, int out_size)
{
    const float4* x4 = (const float4*)d_in[0];
    const float* pm = (const float*)d_in[1];
    const float* pv = (const float*)d_in[2];
    const float* nv = (const float*)d_in[3];
    float* out = (float*)d_out;
    mean_kernel<<<MEAN_GRID, MEAN_NT>>>(x4);
    score_kernel<<<out_size, NT>>>(pm, pv, nv, out);
}